// round 4
// baseline (speedup 1.0000x reference)
#include <cuda_runtime.h>

#define TP 94
#define NN 128
#define HH 32

__device__ float g_h[TP * NN * HH];

// ---------------------------------------------------------------------------
// Kernel 1: conv stack (unchanged from R2). One block per n, 256 threads.
// ---------------------------------------------------------------------------
__global__ void __launch_bounds__(256) conv_kernel(
    const float* __restrict__ x,
    const float* __restrict__ w1, const float* __restrict__ b1,
    const float* __restrict__ w2, const float* __restrict__ b2,
    const float* __restrict__ w3, const float* __restrict__ b3)
{
    __shared__ float x_s[400];
    __shared__ float w1_s[192], b1_s[16];
    __shared__ float w2_s[1536], b2_s[32];
    __shared__ float w3_s[3072], b3_s[32];
    __shared__ float h1_s[98 * 17];
    __shared__ float h2_s[96 * 33];

    const int n = blockIdx.x;
    const int tid = threadIdx.x;
    const int t = tid & 127;
    const int half = tid >> 7;

    for (int idx = tid; idx < 400;  idx += 256) x_s[idx]  = x[n * 400 + idx];
    for (int idx = tid; idx < 192;  idx += 256) w1_s[idx] = w1[idx];
    for (int idx = tid; idx < 1536; idx += 256) w2_s[idx] = w2[idx];
    for (int idx = tid; idx < 3072; idx += 256) w3_s[idx] = w3[idx];
    if (tid < 16) b1_s[tid] = b1[tid];
    if (tid < 32) { b2_s[tid] = b2[tid]; b3_s[tid] = b3[tid]; }
    __syncthreads();

    if (t < 98) {
        float xv[12];
        #pragma unroll
        for (int k = 0; k < 3; k++)
            #pragma unroll
            for (int i = 0; i < 4; i++)
                xv[k * 4 + i] = x_s[(t + k) * 4 + i];
        const int oc0 = half * 8;
        #pragma unroll
        for (int o = 0; o < 8; o++) {
            int oc = oc0 + o;
            float acc = b1_s[oc];
            #pragma unroll
            for (int i = 0; i < 4; i++)
                #pragma unroll
                for (int k = 0; k < 3; k++)
                    acc += xv[k * 4 + i] * w1_s[(oc * 4 + i) * 3 + k];
            h1_s[t * 17 + oc] = fmaxf(acc, 0.f);
        }
    }
    __syncthreads();

    if (t < 96) {
        const int oc0 = half * 16;
        float acc[16];
        #pragma unroll
        for (int o = 0; o < 16; o++) acc[o] = b2_s[oc0 + o];
        for (int ic = 0; ic < 16; ic++) {
            float h0 = h1_s[(t + 0) * 17 + ic];
            float h1v = h1_s[(t + 1) * 17 + ic];
            float h2v = h1_s[(t + 2) * 17 + ic];
            #pragma unroll
            for (int o = 0; o < 16; o++) {
                const float* w = &w2_s[((oc0 + o) * 16 + ic) * 3];
                acc[o] += h0 * w[0] + h1v * w[1] + h2v * w[2];
            }
        }
        #pragma unroll
        for (int o = 0; o < 16; o++)
            h2_s[t * 33 + oc0 + o] = fmaxf(acc[o], 0.f);
    }
    __syncthreads();

    if (t < 94) {
        const int oc0 = half * 16;
        float acc[16];
        #pragma unroll
        for (int o = 0; o < 16; o++) acc[o] = b3_s[oc0 + o];
        for (int ic = 0; ic < 32; ic++) {
            float h0 = h2_s[(t + 0) * 33 + ic];
            float h1v = h2_s[(t + 1) * 33 + ic];
            float h2v = h2_s[(t + 2) * 33 + ic];
            #pragma unroll
            for (int o = 0; o < 16; o++) {
                const float* w = &w3_s[((oc0 + o) * 32 + ic) * 3];
                acc[o] += h0 * w[0] + h1v * w[1] + h2v * w[2];
            }
        }
        #pragma unroll
        for (int o = 0; o < 16; o++)
            g_h[(t * NN + n) * HH + oc0 + o] = fmaxf(acc[o], 0.f);
    }
}

// ---------------------------------------------------------------------------
// Kernel 2: one block per t, 512 threads. Row stride 36 -> float4 smem reads.
// P2 uses relu(x) = 0.5*(x+|x|): acc |ej+c| only (2 ops/elem, abs folds into
// FADD source modifier), plus per-row sum S_d.
// ---------------------------------------------------------------------------
__global__ void __launch_bounds__(512) swarm_kernel(
    const float* __restrict__ x,
    const float* __restrict__ We, const float* __restrict__ be,
    const float* __restrict__ Wa, const float* __restrict__ ba,
    const float* __restrict__ Wu, const float* __restrict__ bu,
    const float* __restrict__ Wd, const float* __restrict__ bd,
    float* __restrict__ out)
{
    extern __shared__ float s[];
    float* h_s  = s;            // 128*36 = 4608
    float* ejT  = s + 4608;     // 32*132 = 4224
    float* ci_s = s + 8832;     // 128*32 = 4096
    float* agA  = s + 12928;    // 128*36 = 4608
    float* agB  = s + 17536;    // 128*36 = 4608
    float* upd  = s + 22144;    // 128*36 = 4608
    float* We_s = s + 26752;    // 2048
    float* be_s = s + 28800;    // 32
    float* Wa_s = s + 28832;    // 1024
    float* ba_s = s + 29856;    // 32
    float* Wu_s = s + 29888;    // 2048
    float* bu_s = s + 31936;    // 32
    float* Wd_s = s + 31968;    // 128
    float* bd_s = s + 32096;    // 4
    // total 32100 floats = 128400 B

    const int t = blockIdx.x;
    const int tid = threadIdx.x;
    const int d = tid & 31;
    const int g = tid >> 5;      // 0..15

    for (int idx = tid; idx < 4096; idx += 512) {
        int i = idx >> 5, c = idx & 31;
        h_s[i * 36 + c] = g_h[t * 4096 + idx];
    }
    for (int idx = tid; idx < 2048; idx += 512) We_s[idx] = We[idx];
    for (int idx = tid; idx < 2048; idx += 512) Wu_s[idx] = Wu[idx];
    for (int idx = tid; idx < 1024; idx += 512) Wa_s[idx] = Wa[idx];
    if (tid < 32) { be_s[tid] = be[tid]; ba_s[tid] = ba[tid]; bu_s[tid] = bu[tid]; }
    else if (tid >= 64 && tid < 192) Wd_s[tid - 64] = Wd[tid - 64];
    else if (tid >= 192 && tid < 196) bd_s[tid - 192] = bd[tid - 192];
    __syncthreads();

    // P1: ejT[d][j], ci[j][d] = ei + be.  float4 h loads, We loads hoisted.
    {
        float aej[8], aei[8];
        float bev = be_s[d];
        #pragma unroll
        for (int ii = 0; ii < 8; ii++) { aej[ii] = 0.f; aei[ii] = bev; }
        #pragma unroll
        for (int c4 = 0; c4 < 8; c4++) {
            float4 hv[8];
            #pragma unroll
            for (int ii = 0; ii < 8; ii++)
                hv[ii] = *(const float4*)&h_s[(g + 16 * ii) * 36 + 4 * c4];
            #pragma unroll
            for (int k = 0; k < 4; k++) {
                int c = 4 * c4 + k;
                float wj = We_s[c * 32 + d];
                float wi = We_s[(32 + c) * 32 + d];
                #pragma unroll
                for (int ii = 0; ii < 8; ii++) {
                    float hvv = (k == 0) ? hv[ii].x : (k == 1) ? hv[ii].y
                              : (k == 2) ? hv[ii].z : hv[ii].w;
                    aej[ii] += hvv * wj;
                    aei[ii] += hvv * wi;
                }
            }
        }
        #pragma unroll
        for (int ii = 0; ii < 8; ii++) {
            int j = g + 16 * ii;
            ejT[d * 132 + j] = aej[ii];
            ci_s[j * 32 + d] = aei[ii];
        }
    }
    __syncthreads();

    // P2: agg0[i][d] = 0.5*(S_d + 128*c_i + Sum_j |ej_j + c_i|) - relu(ej_i+c_i)
    {
        float accA[8], cc[8];
        #pragma unroll
        for (int ii = 0; ii < 8; ii++) {
            cc[ii] = ci_s[(g + 16 * ii) * 32 + d];
            accA[ii] = 0.f;
        }
        float S = 0.f;
        const float4* row = (const float4*)&ejT[d * 132];
        #pragma unroll 8
        for (int j4 = 0; j4 < 32; j4++) {
            float4 v = row[j4];
            S += (v.x + v.y) + (v.z + v.w);
            #pragma unroll
            for (int ii = 0; ii < 8; ii++) {
                accA[ii] += fabsf(v.x + cc[ii]);
                accA[ii] += fabsf(v.y + cc[ii]);
                accA[ii] += fabsf(v.z + cc[ii]);
                accA[ii] += fabsf(v.w + cc[ii]);
            }
        }
        #pragma unroll
        for (int ii = 0; ii < 8; ii++) {
            int i = g + 16 * ii;
            float diag = fmaxf(ejT[d * 132 + i] + cc[ii], 0.f);
            float r = 0.5f * (S + 128.f * cc[ii] + accA[ii]) - diag;
            agA[i * 36 + d] = r;
        }
    }
    __syncthreads();

    // P3: agg = relu(agg0 @ Wa + ba), float4 agA loads
    {
        float acc[8];
        float bav = ba_s[d];
        #pragma unroll
        for (int ii = 0; ii < 8; ii++) acc[ii] = bav;
        #pragma unroll
        for (int c4 = 0; c4 < 8; c4++) {
            float4 av[8];
            #pragma unroll
            for (int ii = 0; ii < 8; ii++)
                av[ii] = *(const float4*)&agA[(g + 16 * ii) * 36 + 4 * c4];
            #pragma unroll
            for (int k = 0; k < 4; k++) {
                int c = 4 * c4 + k;
                float w = Wa_s[c * 32 + d];
                #pragma unroll
                for (int ii = 0; ii < 8; ii++) {
                    float avv = (k == 0) ? av[ii].x : (k == 1) ? av[ii].y
                              : (k == 2) ? av[ii].z : av[ii].w;
                    acc[ii] += avv * w;
                }
            }
        }
        #pragma unroll
        for (int ii = 0; ii < 8; ii++)
            agB[(g + 16 * ii) * 36 + d] = fmaxf(acc[ii], 0.f);
    }
    __syncthreads();

    // P4: upd = relu(h @ Wu[:H] + agg @ Wu[H:] + bu), float4 loads
    {
        float acc[8];
        float buv = bu_s[d];
        #pragma unroll
        for (int ii = 0; ii < 8; ii++) acc[ii] = buv;
        #pragma unroll
        for (int c4 = 0; c4 < 8; c4++) {
            float4 hv[8], av[8];
            #pragma unroll
            for (int ii = 0; ii < 8; ii++) {
                int r = (g + 16 * ii) * 36 + 4 * c4;
                hv[ii] = *(const float4*)&h_s[r];
                av[ii] = *(const float4*)&agB[r];
            }
            #pragma unroll
            for (int k = 0; k < 4; k++) {
                int c = 4 * c4 + k;
                float wh = Wu_s[c * 32 + d];
                float wa = Wu_s[(32 + c) * 32 + d];
                #pragma unroll
                for (int ii = 0; ii < 8; ii++) {
                    float hvv = (k == 0) ? hv[ii].x : (k == 1) ? hv[ii].y
                              : (k == 2) ? hv[ii].z : hv[ii].w;
                    float avv = (k == 0) ? av[ii].x : (k == 1) ? av[ii].y
                              : (k == 2) ? av[ii].z : av[ii].w;
                    acc[ii] += hvv * wh;
                    acc[ii] += avv * wa;
                }
            }
        }
        #pragma unroll
        for (int ii = 0; ii < 8; ii++)
            upd[(g + 16 * ii) * 36 + d] = fmaxf(acc[ii], 0.f);
    }
    __syncthreads();

    // P5: dec = upd @ Wd + bd;  out = x[:, 6+t] + dec
    {
        int i = tid >> 2, dd = tid & 3;
        float acc = bd_s[dd];
        #pragma unroll
        for (int dc = 0; dc < 32; dc++)
            acc += upd[i * 36 + dc] * Wd_s[dc * 4 + dd];
        out[(i * TP + t) * 4 + dd] = x[(i * 100 + 6 + t) * 4 + dd] + acc;
    }
}

// ---------------------------------------------------------------------------
extern "C" void kernel_launch(void* const* d_in, const int* in_sizes, int n_in,
                              void* d_out, int out_size)
{
    const float* x  = (const float*)d_in[0];
    const float* w1 = (const float*)d_in[1];
    const float* b1 = (const float*)d_in[2];
    const float* w2 = (const float*)d_in[3];
    const float* b2 = (const float*)d_in[4];
    const float* w3 = (const float*)d_in[5];
    const float* b3 = (const float*)d_in[6];
    const float* We = (const float*)d_in[7];
    const float* be = (const float*)d_in[8];
    const float* Wa = (const float*)d_in[9];
    const float* ba = (const float*)d_in[10];
    const float* Wu = (const float*)d_in[11];
    const float* bu = (const float*)d_in[12];
    const float* Wd = (const float*)d_in[13];
    const float* bd = (const float*)d_in[14];
    float* out = (float*)d_out;

    cudaFuncSetAttribute(swarm_kernel,
                         cudaFuncAttributeMaxDynamicSharedMemorySize, 32100 * 4);

    conv_kernel<<<128, 256>>>(x, w1, b1, w2, b2, w3, b3);
    swarm_kernel<<<94, 512, 32100 * 4>>>(x, We, be, Wa, ba, Wu, bu, Wd, bd, out);
}

// round 6
// speedup vs baseline: 1.4604x; 1.4604x over previous
#include <cuda_runtime.h>

#define TP 94
#define NN 128
#define HH 32

__device__ float g_h[TP * NN * HH];

// ---------------------------------------------------------------------------
// Kernel 1: conv stack. One block per n, 512 threads: quarter = tid>>7 splits
// output channels (4/8/8 oc per thread per stage) -> 4 warps/SMSP.
// ---------------------------------------------------------------------------
__global__ void __launch_bounds__(512) conv_kernel(
    const float* __restrict__ x,
    const float* __restrict__ w1, const float* __restrict__ b1,
    const float* __restrict__ w2, const float* __restrict__ b2,
    const float* __restrict__ w3, const float* __restrict__ b3)
{
    __shared__ float x_s[400];
    __shared__ float w1_s[192], b1_s[16];
    __shared__ float w2_s[1536], b2_s[32];
    __shared__ float w3_s[3072], b3_s[32];
    __shared__ float h1_s[98 * 17];
    __shared__ float h2_s[96 * 33];

    const int n = blockIdx.x;
    const int tid = threadIdx.x;
    const int t = tid & 127;
    const int q = tid >> 7;          // 0..3

    for (int idx = tid; idx < 400;  idx += 512) x_s[idx]  = x[n * 400 + idx];
    for (int idx = tid; idx < 192;  idx += 512) w1_s[idx] = w1[idx];
    for (int idx = tid; idx < 1536; idx += 512) w2_s[idx] = w2[idx];
    for (int idx = tid; idx < 3072; idx += 512) w3_s[idx] = w3[idx];
    if (tid < 16) b1_s[tid] = b1[tid];
    if (tid < 32) { b2_s[tid] = b2[tid]; b3_s[tid] = b3[tid]; }
    __syncthreads();

    // Stage 1: conv1 4->16, T 100->98.  4 oc per thread.
    if (t < 98) {
        float xv[12];
        #pragma unroll
        for (int k = 0; k < 3; k++)
            #pragma unroll
            for (int i = 0; i < 4; i++)
                xv[k * 4 + i] = x_s[(t + k) * 4 + i];
        const int oc0 = q * 4;
        #pragma unroll
        for (int o = 0; o < 4; o++) {
            int oc = oc0 + o;
            float acc = b1_s[oc];
            #pragma unroll
            for (int i = 0; i < 4; i++)
                #pragma unroll
                for (int k = 0; k < 3; k++)
                    acc += xv[k * 4 + i] * w1_s[(oc * 4 + i) * 3 + k];
            h1_s[t * 17 + oc] = fmaxf(acc, 0.f);
        }
    }
    __syncthreads();

    // Stage 2: conv2 16->32, T 98->96.  8 oc per thread.
    if (t < 96) {
        const int oc0 = q * 8;
        float acc[8];
        #pragma unroll
        for (int o = 0; o < 8; o++) acc[o] = b2_s[oc0 + o];
        for (int ic = 0; ic < 16; ic++) {
            float h0 = h1_s[(t + 0) * 17 + ic];
            float h1v = h1_s[(t + 1) * 17 + ic];
            float h2v = h1_s[(t + 2) * 17 + ic];
            #pragma unroll
            for (int o = 0; o < 8; o++) {
                const float* w = &w2_s[((oc0 + o) * 16 + ic) * 3];
                acc[o] += h0 * w[0] + h1v * w[1] + h2v * w[2];
            }
        }
        #pragma unroll
        for (int o = 0; o < 8; o++)
            h2_s[t * 33 + oc0 + o] = fmaxf(acc[o], 0.f);
    }
    __syncthreads();

    // Stage 3: conv3 32->32, T 96->94.  8 oc per thread.
    if (t < 94) {
        const int oc0 = q * 8;
        float acc[8];
        #pragma unroll
        for (int o = 0; o < 8; o++) acc[o] = b3_s[oc0 + o];
        for (int ic = 0; ic < 32; ic++) {
            float h0 = h2_s[(t + 0) * 33 + ic];
            float h1v = h2_s[(t + 1) * 33 + ic];
            float h2v = h2_s[(t + 2) * 33 + ic];
            #pragma unroll
            for (int o = 0; o < 8; o++) {
                const float* w = &w3_s[((oc0 + o) * 32 + ic) * 3];
                acc[o] += h0 * w[0] + h1v * w[1] + h2v * w[2];
            }
        }
        #pragma unroll
        for (int o = 0; o < 8; o++)
            g_h[(t * NN + n) * HH + oc0 + o] = fmaxf(acc[o], 0.f);
    }
}

// ---------------------------------------------------------------------------
// Kernel 2: R2 structure (register-lean scalar broadcast loads), with the P2
// abs-identity: sum_j relu(ej+c) = 0.5*(S_d + 128c + sum_j |ej+c|).
// ---------------------------------------------------------------------------
__global__ void __launch_bounds__(512) swarm_kernel(
    const float* __restrict__ x,
    const float* __restrict__ We, const float* __restrict__ be,
    const float* __restrict__ Wa, const float* __restrict__ ba,
    const float* __restrict__ Wu, const float* __restrict__ bu,
    const float* __restrict__ Wd, const float* __restrict__ bd,
    float* __restrict__ out)
{
    extern __shared__ float s[];
    float* h_s  = s;           // 128*33 = 4224
    float* ejT  = s + 4224;    // 32*132 = 4224
    float* ci_s = s + 8448;    // 128*32 = 4096
    float* agA  = s + 12544;   // 128*33 = 4224
    float* agB  = s + 16768;   // 128*33 = 4224
    float* upd  = s + 20992;   // 128*33 = 4224
    float* We_s = s + 25216;   // 2048
    float* be_s = s + 27264;   // 32
    float* Wa_s = s + 27296;   // 1024
    float* ba_s = s + 28320;   // 32
    float* Wu_s = s + 28352;   // 2048
    float* bu_s = s + 30400;   // 32
    float* Wd_s = s + 30432;   // 128
    float* bd_s = s + 30560;   // 4
    // total 30564 floats = 122256 B

    const int t = blockIdx.x;
    const int tid = threadIdx.x;
    const int d = tid & 31;
    const int g = tid >> 5;      // 0..15

    for (int idx = tid; idx < 4096; idx += 512) {
        int i = idx >> 5, c = idx & 31;
        h_s[i * 33 + c] = g_h[t * 4096 + idx];
    }
    for (int idx = tid; idx < 2048; idx += 512) We_s[idx] = We[idx];
    for (int idx = tid; idx < 2048; idx += 512) Wu_s[idx] = Wu[idx];
    for (int idx = tid; idx < 1024; idx += 512) Wa_s[idx] = Wa[idx];
    if (tid < 32) { be_s[tid] = be[tid]; ba_s[tid] = ba[tid]; bu_s[tid] = bu[tid]; }
    else if (tid >= 64 && tid < 192) Wd_s[tid - 64] = Wd[tid - 64];
    else if (tid >= 192 && tid < 196) bd_s[tid - 192] = bd[tid - 192];
    __syncthreads();

    // P1: ejT[d][j] and ci[j][d] = ei + be.  8 j per thread; We loads hoisted.
    {
        float aej[8], aei[8];
        float bev = be_s[d];
        #pragma unroll
        for (int ii = 0; ii < 8; ii++) { aej[ii] = 0.f; aei[ii] = bev; }
        #pragma unroll
        for (int c = 0; c < 32; c++) {
            float wj = We_s[c * 32 + d];
            float wi = We_s[(32 + c) * 32 + d];
            #pragma unroll
            for (int ii = 0; ii < 8; ii++) {
                float hv = h_s[(g + 16 * ii) * 33 + c];   // warp broadcast
                aej[ii] += hv * wj;
                aei[ii] += hv * wi;
            }
        }
        #pragma unroll
        for (int ii = 0; ii < 8; ii++) {
            int j = g + 16 * ii;
            ejT[d * 132 + j] = aej[ii];
            ci_s[j * 32 + d] = aei[ii];
        }
    }
    __syncthreads();

    // P2: agg0[i][d] = 0.5*(S_d + 128*c_i + Sum_j |ej_j + c_i|) - relu(ej_i + c_i)
    {
        float acc[8], cc[8];
        #pragma unroll
        for (int ii = 0; ii < 8; ii++) {
            cc[ii] = ci_s[(g + 16 * ii) * 32 + d];
            acc[ii] = 0.f;
        }
        float S = 0.f;
        const float4* row = (const float4*)&ejT[d * 132];
        #pragma unroll 4
        for (int j4 = 0; j4 < 32; j4++) {
            float4 v = row[j4];
            S += (v.x + v.y) + (v.z + v.w);
            #pragma unroll
            for (int ii = 0; ii < 8; ii++) {
                acc[ii] += fabsf(v.x + cc[ii]);
                acc[ii] += fabsf(v.y + cc[ii]);
                acc[ii] += fabsf(v.z + cc[ii]);
                acc[ii] += fabsf(v.w + cc[ii]);
            }
        }
        #pragma unroll
        for (int ii = 0; ii < 8; ii++) {
            int i = g + 16 * ii;
            float diag = fmaxf(ejT[d * 132 + i] + cc[ii], 0.f);
            agA[i * 33 + d] = 0.5f * (S + 128.f * cc[ii] + acc[ii]) - diag;
        }
    }
    __syncthreads();

    // P3: agg = relu(agg0 @ Wa + ba)
    {
        float acc[8];
        float bav = ba_s[d];
        #pragma unroll
        for (int ii = 0; ii < 8; ii++) acc[ii] = bav;
        #pragma unroll
        for (int c = 0; c < 32; c++) {
            float w = Wa_s[c * 32 + d];
            #pragma unroll
            for (int ii = 0; ii < 8; ii++)
                acc[ii] += agA[(g + 16 * ii) * 33 + c] * w;
        }
        #pragma unroll
        for (int ii = 0; ii < 8; ii++)
            agB[(g + 16 * ii) * 33 + d] = fmaxf(acc[ii], 0.f);
    }
    __syncthreads();

    // P4: upd = relu(h @ Wu[:H] + agg @ Wu[H:] + bu)
    {
        float acc[8];
        float buv = bu_s[d];
        #pragma unroll
        for (int ii = 0; ii < 8; ii++) acc[ii] = buv;
        #pragma unroll
        for (int c = 0; c < 32; c++) {
            float wh = Wu_s[c * 32 + d];
            float wa = Wu_s[(32 + c) * 32 + d];
            #pragma unroll
            for (int ii = 0; ii < 8; ii++) {
                int r = (g + 16 * ii) * 33 + c;
                acc[ii] += h_s[r] * wh;
                acc[ii] += agB[r] * wa;
            }
        }
        #pragma unroll
        for (int ii = 0; ii < 8; ii++)
            upd[(g + 16 * ii) * 33 + d] = fmaxf(acc[ii], 0.f);
    }
    __syncthreads();

    // P5: dec = upd @ Wd + bd;  out = x[:, 6+t] + dec
    {
        int i = tid >> 2, dd = tid & 3;
        float acc = bd_s[dd];
        #pragma unroll
        for (int dc = 0; dc < 32; dc++)
            acc += upd[i * 33 + dc] * Wd_s[dc * 4 + dd];
        out[(i * TP + t) * 4 + dd] = x[(i * 100 + 6 + t) * 4 + dd] + acc;
    }
}

// ---------------------------------------------------------------------------
extern "C" void kernel_launch(void* const* d_in, const int* in_sizes, int n_in,
                              void* d_out, int out_size)
{
    const float* x  = (const float*)d_in[0];
    const float* w1 = (const float*)d_in[1];
    const float* b1 = (const float*)d_in[2];
    const float* w2 = (const float*)d_in[3];
    const float* b2 = (const float*)d_in[4];
    const float* w3 = (const float*)d_in[5];
    const float* b3 = (const float*)d_in[6];
    const float* We = (const float*)d_in[7];
    const float* be = (const float*)d_in[8];
    const float* Wa = (const float*)d_in[9];
    const float* ba = (const float*)d_in[10];
    const float* Wu = (const float*)d_in[11];
    const float* bu = (const float*)d_in[12];
    const float* Wd = (const float*)d_in[13];
    const float* bd = (const float*)d_in[14];
    float* out = (float*)d_out;

    cudaFuncSetAttribute(swarm_kernel,
                         cudaFuncAttributeMaxDynamicSharedMemorySize, 30564 * 4);

    conv_kernel<<<128, 512>>>(x, w1, b1, w2, b2, w3, b3);
    swarm_kernel<<<94, 512, 30564 * 4>>>(x, We, be, Wa, ba, Wu, bu, Wd, bd, out);
}